// round 13
// baseline (speedup 1.0000x reference)
#include <cuda_runtime.h>
#include <math.h>

#define N_NODES   1000000
#define K_TOP     10000
#define S_RIP     60
#define D_H       128
#define D_IN      17
#define LN_EPS    1e-5f
#define SUM_BLOCKS 512
#define TIED_CAP  4096

// -------- device scratch (no allocations allowed) --------
__device__ unsigned int g_keys[N_NODES];
__device__ unsigned int g_hist1[2048];
__device__ unsigned int g_hist2[2048];
__device__ unsigned int g_hist3[1024];
// state: [0]=b1 [1]=K1 [2]=b2 [3]=K2 [4]=T [5]=need [6]=tied_count
__device__ unsigned int g_state[8];
__device__ float        g_partials[SUM_BLOCKS * 8];
__device__ int          g_tied[TIED_CAP];
__device__ float        g_x[S_RIP * D_IN];
__device__ float        g_h[S_RIP * D_H];

// -------- pass 1: keys + level-1 histogram (bits [21:31]) --------
__global__ void k_keys_hist1(const float* __restrict__ nf) {
    __shared__ unsigned int sh[2048];
    for (int i = threadIdx.x; i < 2048; i += blockDim.x) sh[i] = 0;
    __syncthreads();
    int stride = gridDim.x * blockDim.x;
    const float4* nf4 = (const float4*)nf;   // row i starts at float 12*i -> float4 3*i
    for (int i = blockIdx.x * blockDim.x + threadIdx.x; i < N_NODES; i += stride) {
        float4 v = nf4[i * 3];               // v.x,v.y,v.z = velocity
        float s = v.x * v.x + v.y * v.y + v.z * v.z;
        unsigned int u = __float_as_uint(s); // s >= 0: uint order == float order
        g_keys[i] = u;
        atomicAdd(&sh[u >> 21], 1u);
    }
    __syncthreads();
    for (int i = threadIdx.x; i < 2048; i += blockDim.x)
        if (sh[i]) atomicAdd(&g_hist1[i], sh[i]);
}

// -------- level-2 histogram over candidate bucket (bits [10:21]) --------
__global__ void k_hist2() {
    __shared__ unsigned int sh[2048];
    for (int i = threadIdx.x; i < 2048; i += blockDim.x) sh[i] = 0;
    __syncthreads();
    unsigned int b1 = g_state[0];
    int stride = gridDim.x * blockDim.x;
    for (int i = blockIdx.x * blockDim.x + threadIdx.x; i < N_NODES; i += stride) {
        unsigned int u = g_keys[i];
        if ((u >> 21) == b1) atomicAdd(&sh[(u >> 10) & 0x7FFu], 1u);
    }
    __syncthreads();
    for (int i = threadIdx.x; i < 2048; i += blockDim.x)
        if (sh[i]) atomicAdd(&g_hist2[i], sh[i]);
}

// -------- level-3 histogram (bits [0:10]) --------
__global__ void k_hist3() {
    __shared__ unsigned int sh[1024];
    for (int i = threadIdx.x; i < 1024; i += blockDim.x) sh[i] = 0;
    __syncthreads();
    unsigned int prefix21 = (g_state[0] << 11) | g_state[2];
    int stride = gridDim.x * blockDim.x;
    for (int i = blockIdx.x * blockDim.x + threadIdx.x; i < N_NODES; i += stride) {
        unsigned int u = g_keys[i];
        if ((u >> 10) == prefix21) atomicAdd(&sh[u & 0x3FFu], 1u);
    }
    __syncthreads();
    for (int i = threadIdx.x; i < 1024; i += blockDim.x)
        if (sh[i]) atomicAdd(&g_hist3[i], sh[i]);
}

// -------- single-block scan: find bucket containing the K-th largest --------
__global__ void k_scan(int level) {
    __shared__ unsigned int csum[256];
    __shared__ unsigned int suf[256];
    const unsigned int* hist = (level == 1) ? g_hist1 : (level == 2) ? g_hist2 : g_hist3;
    int nbins = (level == 3) ? 1024 : 2048;
    unsigned int K = (level == 1) ? (unsigned int)K_TOP
                   : (level == 2) ? g_state[1] : g_state[3];
    int t = threadIdx.x;
    int chunk = nbins / 256;
    unsigned int s = 0;
    for (int b = t * chunk; b < (t + 1) * chunk; b++) s += hist[b];
    csum[t] = s;
    __syncthreads();
    if (t == 0) {
        unsigned int acc = 0;
        for (int c = 255; c >= 0; c--) { suf[c] = acc; acc += csum[c]; }
    }
    __syncthreads();
    // walk own chunk top-down; exactly one thread finds the bucket
    unsigned int cum = suf[t];
    for (int b = (t + 1) * chunk - 1; b >= t * chunk; b--) {
        unsigned int h = hist[b];
        if (cum < K && cum + h >= K) {
            unsigned int rem = K - cum;
            if (level == 1)      { g_state[0] = (unsigned int)b; g_state[1] = rem; }
            else if (level == 2) { g_state[2] = (unsigned int)b; g_state[3] = rem; }
            else {
                g_state[4] = (g_state[0] << 21) | (g_state[2] << 10) | (unsigned int)b;
                g_state[5] = rem;
            }
        }
        cum += h;
    }
}

// -------- reduction: sums over keys > T; collect ties at == T --------
__global__ void k_sum(const float* __restrict__ nf, const float* __restrict__ wp,
                      const float* __restrict__ mp) {
    unsigned int T = g_state[4];
    float acc[8];
#pragma unroll
    for (int c = 0; c < 8; c++) acc[c] = 0.f;
    int stride = gridDim.x * blockDim.x;
    for (int i = blockIdx.x * blockDim.x + threadIdx.x; i < N_NODES; i += stride) {
        unsigned int u = g_keys[i];
        if (u > T) {
            acc[0] += nf[i * 12 + 0];
            acc[1] += nf[i * 12 + 1];
            acc[2] += nf[i * 12 + 2];
            acc[3] += wp[i * 3 + 0];
            acc[4] += wp[i * 3 + 1];
            acc[5] += wp[i * 3 + 2];
            acc[6] += mp[i * 2 + 0];
            acc[7] += mp[i * 2 + 1];
        } else if (u == T) {
            int p = (int)atomicAdd(&g_state[6], 1u);
            if (p < TIED_CAP) g_tied[p] = i;
        }
    }
    __shared__ float red[256];
    for (int c = 0; c < 8; c++) {
        red[threadIdx.x] = acc[c];
        __syncthreads();
        for (int s = 128; s > 0; s >>= 1) {
            if (threadIdx.x < s) red[threadIdx.x] += red[threadIdx.x + s];
            __syncthreads();
        }
        if (threadIdx.x == 0) g_partials[blockIdx.x * 8 + c] = red[0];
        __syncthreads();
    }
}

// -------- finalize: reduce partials, ties (sorted by index), build x + LN0 --------
__global__ void k_finalize(const float* __restrict__ nf, const float* __restrict__ wp,
                           const float* __restrict__ mp, const int* __restrict__ rip,
                           const float* __restrict__ ln0s, const float* __restrict__ ln0b) {
    __shared__ float hv[8];
    int t = threadIdx.x;
    if (t < 8) {
        float a = 0.f;
        for (int b = 0; b < SUM_BLOCKS; b++) a += g_partials[b * 8 + t];
        hv[t] = a;
    }
    __syncthreads();
    if (t == 0) {
        int cnt = (int)g_state[6];
        if (cnt > TIED_CAP) cnt = TIED_CAP;
        int need = (int)g_state[5];
        // insertion sort ascending -> matches stable lowest-index tie-break
        for (int i = 1; i < cnt; i++) {
            int v = g_tied[i];
            int j = i - 1;
            while (j >= 0 && g_tied[j] > v) { g_tied[j + 1] = g_tied[j]; j--; }
            g_tied[j + 1] = v;
        }
        for (int i = 0; i < need && i < cnt; i++) {
            int idx = g_tied[i];
            hv[0] += nf[idx * 12 + 0];
            hv[1] += nf[idx * 12 + 1];
            hv[2] += nf[idx * 12 + 2];
            hv[3] += wp[idx * 3 + 0];
            hv[4] += wp[idx * 3 + 1];
            hv[5] += wp[idx * 3 + 2];
            hv[6] += mp[idx * 2 + 0];
            hv[7] += mp[idx * 2 + 1];
        }
    }
    __syncthreads();
    if (t < S_RIP) {
        int r = rip[t];
        float x[D_IN];
        x[0] = hv[0]; x[1] = hv[1]; x[2] = hv[2];
        x[3] = hv[0]; x[4] = hv[1]; x[5] = hv[2];
        x[6] = hv[0]; x[7] = hv[1]; x[8] = hv[2];
        x[9]  = nf[r * 12 + 0];
        x[10] = nf[r * 12 + 1];
        x[11] = nf[r * 12 + 2];
        x[12] = wp[r * 3 + 0] - hv[3];
        x[13] = wp[r * 3 + 1] - hv[4];
        x[14] = wp[r * 3 + 2] - hv[5];
        x[15] = mp[r * 2 + 0] - hv[6];
        x[16] = mp[r * 2 + 1] - hv[7];
        float mu = 0.f;
#pragma unroll
        for (int k = 0; k < D_IN; k++) mu += x[k];
        mu *= (1.0f / D_IN);
        float var = 0.f;
#pragma unroll
        for (int k = 0; k < D_IN; k++) { float d = x[k] - mu; var += d * d; }
        var *= (1.0f / D_IN);
        float inv = rsqrtf(var + LN_EPS);
#pragma unroll
        for (int k = 0; k < D_IN; k++)
            g_x[t * D_IN + k] = (x[k] - mu) * inv * ln0s[k] + ln0b[k];
    }
}

// -------- MLP: 60 blocks x 128 threads, one row per block --------
__global__ void k_mlp(const float* __restrict__ w1, const float* __restrict__ b1,
                      const float* __restrict__ w2, const float* __restrict__ b2,
                      const float* __restrict__ w3, const float* __restrict__ b3,
                      const float* __restrict__ lnfs, const float* __restrict__ lnfb) {
    int row = blockIdx.x;
    int j = threadIdx.x;  // 0..127
    __shared__ float sx[D_IN];
    __shared__ float h1[D_H];
    __shared__ float h2[D_H];
    __shared__ float red[D_H];
    if (j < D_IN) sx[j] = g_x[row * D_IN + j];
    __syncthreads();
    float a = b1[j];
#pragma unroll
    for (int k = 0; k < D_IN; k++) a += sx[k] * w1[k * D_H + j];
    h1[j] = fmaxf(a, 0.f);
    __syncthreads();
    a = b2[j];
#pragma unroll 8
    for (int k = 0; k < D_H; k++) a += h1[k] * w2[k * D_H + j];
    h2[j] = fmaxf(a, 0.f);
    __syncthreads();
    a = b3[j];
#pragma unroll 8
    for (int k = 0; k < D_H; k++) a += h2[k] * w3[k * D_H + j];
    // layernorm over 128
    float val = a;
    red[j] = val;
    __syncthreads();
    for (int s = 64; s > 0; s >>= 1) {
        if (j < s) red[j] += red[j + s];
        __syncthreads();
    }
    float mu = red[0] * (1.0f / D_H);
    __syncthreads();
    float d = val - mu;
    red[j] = d * d;
    __syncthreads();
    for (int s = 64; s > 0; s >>= 1) {
        if (j < s) red[j] += red[j + s];
        __syncthreads();
    }
    float var = red[0] * (1.0f / D_H);
    float out = d * rsqrtf(var + LN_EPS) * lnfs[j] + lnfb[j];
    g_h[row * D_H + j] = out;
}

// -------- bulk copy: batched 256-bit staged streaming copy --------
// Each thread per outer iteration: 4 independent LDG.E.256 (evict-first),
// then 4 STG.E.256 — guarantees MLP>=4 and batches reads before writes.
__global__ void k_copy(double4* __restrict__ dst, const double4* __restrict__ src, int n) {
    int gsz = gridDim.x * blockDim.x;
    int i = blockIdx.x * blockDim.x + threadIdx.x;
    int bigstep = gsz * 4;
    // batched main loop
    for (; i + 3 * gsz < n; i += bigstep) {
        double4 v0 = src[i];
        double4 v1 = src[i + gsz];
        double4 v2 = src[i + 2 * gsz];
        double4 v3 = src[i + 3 * gsz];
        dst[i]           = v0;
        dst[i + gsz]     = v1;
        dst[i + 2 * gsz] = v2;
        dst[i + 3 * gsz] = v3;
    }
    // tail
    for (; i < n; i += gsz) dst[i] = src[i];
}

// remainder floats (out_size not divisible by 8) — copied 1:1
__global__ void k_copy_tail(float* __restrict__ dst, const float* __restrict__ src,
                            int start, int n) {
    int i = start + blockIdx.x * blockDim.x + threadIdx.x;
    if (i < n) dst[i] = src[i];
}

// -------- scatter-add after join; tail resets scratch for next graph replay --------
__global__ void k_scatter(float* __restrict__ out, const int* __restrict__ rip) {
    int row = blockIdx.x;
    int j = threadIdx.x;
    long long r = (long long)rip[row];
    out[r * D_H + j] += g_h[row * D_H + j];
    // zero scratch state for the next replay (60*128 = 7680 threads)
    int gid = row * D_H + j;
    if (gid < 2048) g_hist1[gid] = 0;
    if (gid >= 2048 && gid < 4096) g_hist2[gid - 2048] = 0;
    if (gid >= 4096 && gid < 5120) g_hist3[gid - 4096] = 0;
    if (gid >= 5120 && gid < 5128) g_state[gid - 5120] = 0;
}

extern "C" void kernel_launch(void* const* d_in, const int* in_sizes, int n_in,
                              void* d_out, int out_size) {
    const float* nf   = (const float*)d_in[0];
    const float* wp   = (const float*)d_in[1];
    const float* mp   = (const float*)d_in[2];
    const float* lat  = (const float*)d_in[3];
    const int*   rip  = (const int*)  d_in[4];
    const float* ln0s = (const float*)d_in[5];
    const float* ln0b = (const float*)d_in[6];
    const float* w1   = (const float*)d_in[7];
    const float* b1   = (const float*)d_in[8];
    const float* w2   = (const float*)d_in[9];
    const float* b2   = (const float*)d_in[10];
    const float* w3   = (const float*)d_in[11];
    const float* b3   = (const float*)d_in[12];
    const float* lnfs = (const float*)d_in[13];
    const float* lnfb = (const float*)d_in[14];
    float* out = (float*)d_out;

    // one-time side-stream + events for the parallel copy branch
    static cudaStream_t s2 = nullptr;
    static cudaEvent_t evFork = nullptr, evJoin = nullptr;
    if (!s2) {
        cudaStreamCreateWithFlags(&s2, cudaStreamNonBlocking);
        cudaEventCreateWithFlags(&evFork, cudaEventDisableTiming);
        cudaEventCreateWithFlags(&evJoin, cudaEventDisableTiming);
    }

    // fork: streaming bulk copy runs concurrently with the select/MLP chain
    cudaEventRecord(evFork, 0);
    cudaStreamWaitEvent(s2, evFork, 0);
    int n256 = out_size / 8;                 // double4 elements
    k_copy<<<2048, 256, 0, s2>>>((double4*)out, (const double4*)lat, n256);
    int rem = out_size - n256 * 8;
    if (rem > 0)
        k_copy_tail<<<(rem + 255) / 256, 256, 0, s2>>>(out, lat, n256 * 8, out_size);

    // main chain (branch A) — hidden under the copy
    k_keys_hist1<<<1024, 256>>>(nf);
    k_scan<<<1, 256>>>(1);
    k_hist2<<<512, 256>>>();
    k_scan<<<1, 256>>>(2);
    k_hist3<<<512, 256>>>();
    k_scan<<<1, 256>>>(3);
    k_sum<<<SUM_BLOCKS, 256>>>(nf, wp, mp);
    k_finalize<<<1, 64>>>(nf, wp, mp, rip, ln0s, ln0b);
    k_mlp<<<S_RIP, D_H>>>(w1, b1, w2, b2, w3, b3, lnfs, lnfb);

    // join: scatter-add needs both the copy and the MLP result
    cudaEventRecord(evJoin, s2);
    cudaStreamWaitEvent(0, evJoin, 0);
    k_scatter<<<S_RIP, D_H>>>(out, rip);
}

// round 14
// speedup vs baseline: 1.0317x; 1.0317x over previous
#include <cuda_runtime.h>
#include <math.h>

#define N_NODES   1000000
#define K_TOP     10000
#define S_RIP     60
#define D_H       128
#define D_IN      17
#define LN_EPS    1e-5f
#define SUM_BLOCKS 512
#define TIED_CAP  4096

// -------- device scratch (no allocations allowed) --------
__device__ unsigned int g_keys[N_NODES];
__device__ unsigned int g_hist1[2048];
__device__ unsigned int g_hist2[2048];
__device__ unsigned int g_hist3[1024];
// state: [0]=b1 [1]=K1 [2]=b2 [3]=K2 [4]=T [5]=need [6]=tied_count
__device__ unsigned int g_state[8];
__device__ float        g_partials[SUM_BLOCKS * 8];
__device__ int          g_tied[TIED_CAP];
__device__ float        g_x[S_RIP * D_IN];
__device__ float        g_h[S_RIP * D_H];

// -------- pass 1: keys + level-1 histogram (bits [21:31]) --------
__global__ void k_keys_hist1(const float* __restrict__ nf) {
    __shared__ unsigned int sh[2048];
    for (int i = threadIdx.x; i < 2048; i += blockDim.x) sh[i] = 0;
    __syncthreads();
    int stride = gridDim.x * blockDim.x;
    const float4* nf4 = (const float4*)nf;   // row i starts at float 12*i -> float4 3*i
    for (int i = blockIdx.x * blockDim.x + threadIdx.x; i < N_NODES; i += stride) {
        float4 v = nf4[i * 3];               // v.x,v.y,v.z = velocity
        float s = v.x * v.x + v.y * v.y + v.z * v.z;
        unsigned int u = __float_as_uint(s); // s >= 0: uint order == float order
        g_keys[i] = u;
        atomicAdd(&sh[u >> 21], 1u);
    }
    __syncthreads();
    for (int i = threadIdx.x; i < 2048; i += blockDim.x)
        if (sh[i]) atomicAdd(&g_hist1[i], sh[i]);
}

// -------- level-2 histogram over candidate bucket (bits [10:21]) --------
__global__ void k_hist2() {
    __shared__ unsigned int sh[2048];
    for (int i = threadIdx.x; i < 2048; i += blockDim.x) sh[i] = 0;
    __syncthreads();
    unsigned int b1 = g_state[0];
    int stride = gridDim.x * blockDim.x;
    for (int i = blockIdx.x * blockDim.x + threadIdx.x; i < N_NODES; i += stride) {
        unsigned int u = g_keys[i];
        if ((u >> 21) == b1) atomicAdd(&sh[(u >> 10) & 0x7FFu], 1u);
    }
    __syncthreads();
    for (int i = threadIdx.x; i < 2048; i += blockDim.x)
        if (sh[i]) atomicAdd(&g_hist2[i], sh[i]);
}

// -------- level-3 histogram (bits [0:10]) --------
__global__ void k_hist3() {
    __shared__ unsigned int sh[1024];
    for (int i = threadIdx.x; i < 1024; i += blockDim.x) sh[i] = 0;
    __syncthreads();
    unsigned int prefix21 = (g_state[0] << 11) | g_state[2];
    int stride = gridDim.x * blockDim.x;
    for (int i = blockIdx.x * blockDim.x + threadIdx.x; i < N_NODES; i += stride) {
        unsigned int u = g_keys[i];
        if ((u >> 10) == prefix21) atomicAdd(&sh[u & 0x3FFu], 1u);
    }
    __syncthreads();
    for (int i = threadIdx.x; i < 1024; i += blockDim.x)
        if (sh[i]) atomicAdd(&g_hist3[i], sh[i]);
}

// -------- single-block scan: find bucket containing the K-th largest --------
__global__ void k_scan(int level) {
    __shared__ unsigned int csum[256];
    __shared__ unsigned int suf[256];
    const unsigned int* hist = (level == 1) ? g_hist1 : (level == 2) ? g_hist2 : g_hist3;
    int nbins = (level == 3) ? 1024 : 2048;
    unsigned int K = (level == 1) ? (unsigned int)K_TOP
                   : (level == 2) ? g_state[1] : g_state[3];
    int t = threadIdx.x;
    int chunk = nbins / 256;
    unsigned int s = 0;
    for (int b = t * chunk; b < (t + 1) * chunk; b++) s += hist[b];
    csum[t] = s;
    __syncthreads();
    if (t == 0) {
        unsigned int acc = 0;
        for (int c = 255; c >= 0; c--) { suf[c] = acc; acc += csum[c]; }
    }
    __syncthreads();
    // walk own chunk top-down; exactly one thread finds the bucket
    unsigned int cum = suf[t];
    for (int b = (t + 1) * chunk - 1; b >= t * chunk; b--) {
        unsigned int h = hist[b];
        if (cum < K && cum + h >= K) {
            unsigned int rem = K - cum;
            if (level == 1)      { g_state[0] = (unsigned int)b; g_state[1] = rem; }
            else if (level == 2) { g_state[2] = (unsigned int)b; g_state[3] = rem; }
            else {
                g_state[4] = (g_state[0] << 21) | (g_state[2] << 10) | (unsigned int)b;
                g_state[5] = rem;
            }
        }
        cum += h;
    }
}

// -------- reduction: sums over keys > T; collect ties at == T --------
__global__ void k_sum(const float* __restrict__ nf, const float* __restrict__ wp,
                      const float* __restrict__ mp) {
    unsigned int T = g_state[4];
    float acc[8];
#pragma unroll
    for (int c = 0; c < 8; c++) acc[c] = 0.f;
    int stride = gridDim.x * blockDim.x;
    for (int i = blockIdx.x * blockDim.x + threadIdx.x; i < N_NODES; i += stride) {
        unsigned int u = g_keys[i];
        if (u > T) {
            acc[0] += nf[i * 12 + 0];
            acc[1] += nf[i * 12 + 1];
            acc[2] += nf[i * 12 + 2];
            acc[3] += wp[i * 3 + 0];
            acc[4] += wp[i * 3 + 1];
            acc[5] += wp[i * 3 + 2];
            acc[6] += mp[i * 2 + 0];
            acc[7] += mp[i * 2 + 1];
        } else if (u == T) {
            int p = (int)atomicAdd(&g_state[6], 1u);
            if (p < TIED_CAP) g_tied[p] = i;
        }
    }
    __shared__ float red[256];
    for (int c = 0; c < 8; c++) {
        red[threadIdx.x] = acc[c];
        __syncthreads();
        for (int s = 128; s > 0; s >>= 1) {
            if (threadIdx.x < s) red[threadIdx.x] += red[threadIdx.x + s];
            __syncthreads();
        }
        if (threadIdx.x == 0) g_partials[blockIdx.x * 8 + c] = red[0];
        __syncthreads();
    }
}

// -------- finalize: reduce partials, ties (sorted by index), build x + LN0 --------
__global__ void k_finalize(const float* __restrict__ nf, const float* __restrict__ wp,
                           const float* __restrict__ mp, const int* __restrict__ rip,
                           const float* __restrict__ ln0s, const float* __restrict__ ln0b) {
    __shared__ float hv[8];
    int t = threadIdx.x;
    if (t < 8) {
        float a = 0.f;
        for (int b = 0; b < SUM_BLOCKS; b++) a += g_partials[b * 8 + t];
        hv[t] = a;
    }
    __syncthreads();
    if (t == 0) {
        int cnt = (int)g_state[6];
        if (cnt > TIED_CAP) cnt = TIED_CAP;
        int need = (int)g_state[5];
        // insertion sort ascending -> matches stable lowest-index tie-break
        for (int i = 1; i < cnt; i++) {
            int v = g_tied[i];
            int j = i - 1;
            while (j >= 0 && g_tied[j] > v) { g_tied[j + 1] = g_tied[j]; j--; }
            g_tied[j + 1] = v;
        }
        for (int i = 0; i < need && i < cnt; i++) {
            int idx = g_tied[i];
            hv[0] += nf[idx * 12 + 0];
            hv[1] += nf[idx * 12 + 1];
            hv[2] += nf[idx * 12 + 2];
            hv[3] += wp[idx * 3 + 0];
            hv[4] += wp[idx * 3 + 1];
            hv[5] += wp[idx * 3 + 2];
            hv[6] += mp[idx * 2 + 0];
            hv[7] += mp[idx * 2 + 1];
        }
    }
    __syncthreads();
    if (t < S_RIP) {
        int r = rip[t];
        float x[D_IN];
        x[0] = hv[0]; x[1] = hv[1]; x[2] = hv[2];
        x[3] = hv[0]; x[4] = hv[1]; x[5] = hv[2];
        x[6] = hv[0]; x[7] = hv[1]; x[8] = hv[2];
        x[9]  = nf[r * 12 + 0];
        x[10] = nf[r * 12 + 1];
        x[11] = nf[r * 12 + 2];
        x[12] = wp[r * 3 + 0] - hv[3];
        x[13] = wp[r * 3 + 1] - hv[4];
        x[14] = wp[r * 3 + 2] - hv[5];
        x[15] = mp[r * 2 + 0] - hv[6];
        x[16] = mp[r * 2 + 1] - hv[7];
        float mu = 0.f;
#pragma unroll
        for (int k = 0; k < D_IN; k++) mu += x[k];
        mu *= (1.0f / D_IN);
        float var = 0.f;
#pragma unroll
        for (int k = 0; k < D_IN; k++) { float d = x[k] - mu; var += d * d; }
        var *= (1.0f / D_IN);
        float inv = rsqrtf(var + LN_EPS);
#pragma unroll
        for (int k = 0; k < D_IN; k++)
            g_x[t * D_IN + k] = (x[k] - mu) * inv * ln0s[k] + ln0b[k];
    }
}

// -------- MLP: 60 blocks x 128 threads, one row per block --------
__global__ void k_mlp(const float* __restrict__ w1, const float* __restrict__ b1,
                      const float* __restrict__ w2, const float* __restrict__ b2,
                      const float* __restrict__ w3, const float* __restrict__ b3,
                      const float* __restrict__ lnfs, const float* __restrict__ lnfb) {
    int row = blockIdx.x;
    int j = threadIdx.x;  // 0..127
    __shared__ float sx[D_IN];
    __shared__ float h1[D_H];
    __shared__ float h2[D_H];
    __shared__ float red[D_H];
    if (j < D_IN) sx[j] = g_x[row * D_IN + j];
    __syncthreads();
    float a = b1[j];
#pragma unroll
    for (int k = 0; k < D_IN; k++) a += sx[k] * w1[k * D_H + j];
    h1[j] = fmaxf(a, 0.f);
    __syncthreads();
    a = b2[j];
#pragma unroll 8
    for (int k = 0; k < D_H; k++) a += h1[k] * w2[k * D_H + j];
    h2[j] = fmaxf(a, 0.f);
    __syncthreads();
    a = b3[j];
#pragma unroll 8
    for (int k = 0; k < D_H; k++) a += h2[k] * w3[k * D_H + j];
    // layernorm over 128
    float val = a;
    red[j] = val;
    __syncthreads();
    for (int s = 64; s > 0; s >>= 1) {
        if (j < s) red[j] += red[j + s];
        __syncthreads();
    }
    float mu = red[0] * (1.0f / D_H);
    __syncthreads();
    float d = val - mu;
    red[j] = d * d;
    __syncthreads();
    for (int s = 64; s > 0; s >>= 1) {
        if (j < s) red[j] += red[j + s];
        __syncthreads();
    }
    float var = red[0] * (1.0f / D_H);
    float out = d * rsqrtf(var + LN_EPS) * lnfs[j] + lnfb[j];
    g_h[row * D_H + j] = out;
}

// -------- bulk copy: float4, streaming load + WRITE-THROUGH store --------
// __ldcs: evict-first read (no L2 pollution). __stwt: write-through store —
// no dirty-line allocation/eviction on the write path.
__global__ void k_copy(float4* __restrict__ dst, const float4* __restrict__ src, int n4) {
    int i = blockIdx.x * blockDim.x + threadIdx.x;
    int stride = gridDim.x * blockDim.x;
#pragma unroll 4
    for (; i < n4; i += stride) {
        float4 v = __ldcs(&src[i]);
        __stwt(&dst[i], v);
    }
}

// -------- scatter-add after join; tail resets scratch for next graph replay --------
__global__ void k_scatter(float* __restrict__ out, const int* __restrict__ rip) {
    int row = blockIdx.x;
    int j = threadIdx.x;
    long long r = (long long)rip[row];
    out[r * D_H + j] += g_h[row * D_H + j];
    // zero scratch state for the next replay (60*128 = 7680 threads)
    int gid = row * D_H + j;
    if (gid < 2048) g_hist1[gid] = 0;
    if (gid >= 2048 && gid < 4096) g_hist2[gid - 2048] = 0;
    if (gid >= 4096 && gid < 5120) g_hist3[gid - 4096] = 0;
    if (gid >= 5120 && gid < 5128) g_state[gid - 5120] = 0;
}

extern "C" void kernel_launch(void* const* d_in, const int* in_sizes, int n_in,
                              void* d_out, int out_size) {
    const float* nf   = (const float*)d_in[0];
    const float* wp   = (const float*)d_in[1];
    const float* mp   = (const float*)d_in[2];
    const float* lat  = (const float*)d_in[3];
    const int*   rip  = (const int*)  d_in[4];
    const float* ln0s = (const float*)d_in[5];
    const float* ln0b = (const float*)d_in[6];
    const float* w1   = (const float*)d_in[7];
    const float* b1   = (const float*)d_in[8];
    const float* w2   = (const float*)d_in[9];
    const float* b2   = (const float*)d_in[10];
    const float* w3   = (const float*)d_in[11];
    const float* b3   = (const float*)d_in[12];
    const float* lnfs = (const float*)d_in[13];
    const float* lnfb = (const float*)d_in[14];
    float* out = (float*)d_out;

    // one-time side-stream + events for the parallel copy branch
    static cudaStream_t s2 = nullptr;
    static cudaEvent_t evFork = nullptr, evJoin = nullptr;
    if (!s2) {
        cudaStreamCreateWithFlags(&s2, cudaStreamNonBlocking);
        cudaEventCreateWithFlags(&evFork, cudaEventDisableTiming);
        cudaEventCreateWithFlags(&evJoin, cudaEventDisableTiming);
    }

    // fork: streaming bulk copy runs concurrently with the select/MLP chain
    cudaEventRecord(evFork, 0);
    cudaStreamWaitEvent(s2, evFork, 0);
    k_copy<<<2368, 256, 0, s2>>>((float4*)out, (const float4*)lat, out_size / 4);

    // main chain (branch A) — hidden under the copy
    k_keys_hist1<<<1024, 256>>>(nf);
    k_scan<<<1, 256>>>(1);
    k_hist2<<<512, 256>>>();
    k_scan<<<1, 256>>>(2);
    k_hist3<<<512, 256>>>();
    k_scan<<<1, 256>>>(3);
    k_sum<<<SUM_BLOCKS, 256>>>(nf, wp, mp);
    k_finalize<<<1, 64>>>(nf, wp, mp, rip, ln0s, ln0b);
    k_mlp<<<S_RIP, D_H>>>(w1, b1, w2, b2, w3, b3, lnfs, lnfb);

    // join: scatter-add needs both the copy and the MLP result
    cudaEventRecord(evJoin, s2);
    cudaStreamWaitEvent(0, evJoin, 0);
    k_scatter<<<S_RIP, D_H>>>(out, rip);
}

// round 15
// speedup vs baseline: 1.1664x; 1.1305x over previous
#include <cuda_runtime.h>
#include <math.h>

#define N_NODES   1000000
#define K_TOP     10000
#define S_RIP     60
#define D_H       128
#define D_IN      17
#define LN_EPS    1e-5f
#define SUM_BLOCKS 512
#define TIED_CAP  4096

#define NSTAGE    4
#define CP_CHUNK  8192

// -------- device scratch (no allocations allowed) --------
__device__ unsigned int g_keys[N_NODES];
__device__ unsigned int g_hist1[2048];
__device__ unsigned int g_hist2[2048];
__device__ unsigned int g_hist3[1024];
// state: [0]=b1 [1]=K1 [2]=b2 [3]=K2 [4]=T [5]=need [6]=tied_count
__device__ unsigned int g_state[8];
__device__ float        g_partials[SUM_BLOCKS * 8];
__device__ int          g_tied[TIED_CAP];
__device__ float        g_x[S_RIP * D_IN];
__device__ float        g_h[S_RIP * D_H];

// -------- pass 1: keys + level-1 histogram (bits [21:31]) --------
__global__ void k_keys_hist1(const float* __restrict__ nf) {
    __shared__ unsigned int sh[2048];
    for (int i = threadIdx.x; i < 2048; i += blockDim.x) sh[i] = 0;
    __syncthreads();
    int stride = gridDim.x * blockDim.x;
    const float4* nf4 = (const float4*)nf;   // row i starts at float 12*i -> float4 3*i
    for (int i = blockIdx.x * blockDim.x + threadIdx.x; i < N_NODES; i += stride) {
        float4 v = nf4[i * 3];               // v.x,v.y,v.z = velocity
        float s = v.x * v.x + v.y * v.y + v.z * v.z;
        unsigned int u = __float_as_uint(s); // s >= 0: uint order == float order
        g_keys[i] = u;
        atomicAdd(&sh[u >> 21], 1u);
    }
    __syncthreads();
    for (int i = threadIdx.x; i < 2048; i += blockDim.x)
        if (sh[i]) atomicAdd(&g_hist1[i], sh[i]);
}

// -------- level-2 histogram over candidate bucket (bits [10:21]) --------
__global__ void k_hist2() {
    __shared__ unsigned int sh[2048];
    for (int i = threadIdx.x; i < 2048; i += blockDim.x) sh[i] = 0;
    __syncthreads();
    unsigned int b1 = g_state[0];
    int stride = gridDim.x * blockDim.x;
    for (int i = blockIdx.x * blockDim.x + threadIdx.x; i < N_NODES; i += stride) {
        unsigned int u = g_keys[i];
        if ((u >> 21) == b1) atomicAdd(&sh[(u >> 10) & 0x7FFu], 1u);
    }
    __syncthreads();
    for (int i = threadIdx.x; i < 2048; i += blockDim.x)
        if (sh[i]) atomicAdd(&g_hist2[i], sh[i]);
}

// -------- level-3 histogram (bits [0:10]) --------
__global__ void k_hist3() {
    __shared__ unsigned int sh[1024];
    for (int i = threadIdx.x; i < 1024; i += blockDim.x) sh[i] = 0;
    __syncthreads();
    unsigned int prefix21 = (g_state[0] << 11) | g_state[2];
    int stride = gridDim.x * blockDim.x;
    for (int i = blockIdx.x * blockDim.x + threadIdx.x; i < N_NODES; i += stride) {
        unsigned int u = g_keys[i];
        if ((u >> 10) == prefix21) atomicAdd(&sh[u & 0x3FFu], 1u);
    }
    __syncthreads();
    for (int i = threadIdx.x; i < 1024; i += blockDim.x)
        if (sh[i]) atomicAdd(&g_hist3[i], sh[i]);
}

// -------- single-block scan: find bucket containing the K-th largest --------
__global__ void k_scan(int level) {
    __shared__ unsigned int csum[256];
    __shared__ unsigned int suf[256];
    const unsigned int* hist = (level == 1) ? g_hist1 : (level == 2) ? g_hist2 : g_hist3;
    int nbins = (level == 3) ? 1024 : 2048;
    unsigned int K = (level == 1) ? (unsigned int)K_TOP
                   : (level == 2) ? g_state[1] : g_state[3];
    int t = threadIdx.x;
    int chunk = nbins / 256;
    unsigned int s = 0;
    for (int b = t * chunk; b < (t + 1) * chunk; b++) s += hist[b];
    csum[t] = s;
    __syncthreads();
    if (t == 0) {
        unsigned int acc = 0;
        for (int c = 255; c >= 0; c--) { suf[c] = acc; acc += csum[c]; }
    }
    __syncthreads();
    // walk own chunk top-down; exactly one thread finds the bucket
    unsigned int cum = suf[t];
    for (int b = (t + 1) * chunk - 1; b >= t * chunk; b--) {
        unsigned int h = hist[b];
        if (cum < K && cum + h >= K) {
            unsigned int rem = K - cum;
            if (level == 1)      { g_state[0] = (unsigned int)b; g_state[1] = rem; }
            else if (level == 2) { g_state[2] = (unsigned int)b; g_state[3] = rem; }
            else {
                g_state[4] = (g_state[0] << 21) | (g_state[2] << 10) | (unsigned int)b;
                g_state[5] = rem;
            }
        }
        cum += h;
    }
}

// -------- reduction: sums over keys > T; collect ties at == T --------
__global__ void k_sum(const float* __restrict__ nf, const float* __restrict__ wp,
                      const float* __restrict__ mp) {
    unsigned int T = g_state[4];
    float acc[8];
#pragma unroll
    for (int c = 0; c < 8; c++) acc[c] = 0.f;
    int stride = gridDim.x * blockDim.x;
    for (int i = blockIdx.x * blockDim.x + threadIdx.x; i < N_NODES; i += stride) {
        unsigned int u = g_keys[i];
        if (u > T) {
            acc[0] += nf[i * 12 + 0];
            acc[1] += nf[i * 12 + 1];
            acc[2] += nf[i * 12 + 2];
            acc[3] += wp[i * 3 + 0];
            acc[4] += wp[i * 3 + 1];
            acc[5] += wp[i * 3 + 2];
            acc[6] += mp[i * 2 + 0];
            acc[7] += mp[i * 2 + 1];
        } else if (u == T) {
            int p = (int)atomicAdd(&g_state[6], 1u);
            if (p < TIED_CAP) g_tied[p] = i;
        }
    }
    __shared__ float red[256];
    for (int c = 0; c < 8; c++) {
        red[threadIdx.x] = acc[c];
        __syncthreads();
        for (int s = 128; s > 0; s >>= 1) {
            if (threadIdx.x < s) red[threadIdx.x] += red[threadIdx.x + s];
            __syncthreads();
        }
        if (threadIdx.x == 0) g_partials[blockIdx.x * 8 + c] = red[0];
        __syncthreads();
    }
}

// -------- finalize: reduce partials, ties (sorted by index), build x + LN0 --------
__global__ void k_finalize(const float* __restrict__ nf, const float* __restrict__ wp,
                           const float* __restrict__ mp, const int* __restrict__ rip,
                           const float* __restrict__ ln0s, const float* __restrict__ ln0b) {
    __shared__ float hv[8];
    int t = threadIdx.x;
    if (t < 8) {
        float a = 0.f;
        for (int b = 0; b < SUM_BLOCKS; b++) a += g_partials[b * 8 + t];
        hv[t] = a;
    }
    __syncthreads();
    if (t == 0) {
        int cnt = (int)g_state[6];
        if (cnt > TIED_CAP) cnt = TIED_CAP;
        int need = (int)g_state[5];
        // insertion sort ascending -> matches stable lowest-index tie-break
        for (int i = 1; i < cnt; i++) {
            int v = g_tied[i];
            int j = i - 1;
            while (j >= 0 && g_tied[j] > v) { g_tied[j + 1] = g_tied[j]; j--; }
            g_tied[j + 1] = v;
        }
        for (int i = 0; i < need && i < cnt; i++) {
            int idx = g_tied[i];
            hv[0] += nf[idx * 12 + 0];
            hv[1] += nf[idx * 12 + 1];
            hv[2] += nf[idx * 12 + 2];
            hv[3] += wp[idx * 3 + 0];
            hv[4] += wp[idx * 3 + 1];
            hv[5] += wp[idx * 3 + 2];
            hv[6] += mp[idx * 2 + 0];
            hv[7] += mp[idx * 2 + 1];
        }
    }
    __syncthreads();
    if (t < S_RIP) {
        int r = rip[t];
        float x[D_IN];
        x[0] = hv[0]; x[1] = hv[1]; x[2] = hv[2];
        x[3] = hv[0]; x[4] = hv[1]; x[5] = hv[2];
        x[6] = hv[0]; x[7] = hv[1]; x[8] = hv[2];
        x[9]  = nf[r * 12 + 0];
        x[10] = nf[r * 12 + 1];
        x[11] = nf[r * 12 + 2];
        x[12] = wp[r * 3 + 0] - hv[3];
        x[13] = wp[r * 3 + 1] - hv[4];
        x[14] = wp[r * 3 + 2] - hv[5];
        x[15] = mp[r * 2 + 0] - hv[6];
        x[16] = mp[r * 2 + 1] - hv[7];
        float mu = 0.f;
#pragma unroll
        for (int k = 0; k < D_IN; k++) mu += x[k];
        mu *= (1.0f / D_IN);
        float var = 0.f;
#pragma unroll
        for (int k = 0; k < D_IN; k++) { float d = x[k] - mu; var += d * d; }
        var *= (1.0f / D_IN);
        float inv = rsqrtf(var + LN_EPS);
#pragma unroll
        for (int k = 0; k < D_IN; k++)
            g_x[t * D_IN + k] = (x[k] - mu) * inv * ln0s[k] + ln0b[k];
    }
}

// -------- MLP: 60 blocks x 128 threads, one row per block --------
__global__ void k_mlp(const float* __restrict__ w1, const float* __restrict__ b1,
                      const float* __restrict__ w2, const float* __restrict__ b2,
                      const float* __restrict__ w3, const float* __restrict__ b3,
                      const float* __restrict__ lnfs, const float* __restrict__ lnfb) {
    int row = blockIdx.x;
    int j = threadIdx.x;  // 0..127
    __shared__ float sx[D_IN];
    __shared__ float h1[D_H];
    __shared__ float h2[D_H];
    __shared__ float red[D_H];
    if (j < D_IN) sx[j] = g_x[row * D_IN + j];
    __syncthreads();
    float a = b1[j];
#pragma unroll
    for (int k = 0; k < D_IN; k++) a += sx[k] * w1[k * D_H + j];
    h1[j] = fmaxf(a, 0.f);
    __syncthreads();
    a = b2[j];
#pragma unroll 8
    for (int k = 0; k < D_H; k++) a += h1[k] * w2[k * D_H + j];
    h2[j] = fmaxf(a, 0.f);
    __syncthreads();
    a = b3[j];
#pragma unroll 8
    for (int k = 0; k < D_H; k++) a += h2[k] * w3[k * D_H + j];
    // layernorm over 128
    float val = a;
    red[j] = val;
    __syncthreads();
    for (int s = 64; s > 0; s >>= 1) {
        if (j < s) red[j] += red[j + s];
        __syncthreads();
    }
    float mu = red[0] * (1.0f / D_H);
    __syncthreads();
    float d = val - mu;
    red[j] = d * d;
    __syncthreads();
    for (int s = 64; s > 0; s >>= 1) {
        if (j < s) red[j] += red[j + s];
        __syncthreads();
    }
    float var = red[0] * (1.0f / D_H);
    float out = d * rsqrtf(var + LN_EPS) * lnfs[j] + lnfb[j];
    g_h[row * D_H + j] = out;
}

// -------- bulk copy via TMA: cp.async.bulk 8KB bursts, 4-stage SMEM pipeline --------
// One control thread per CTA. Loads complete via mbarrier (complete_tx); stores
// via bulk_group. wait_group.read 0 before buffer reuse (smem-read drain only,
// ~128 cyc per 8KB — the GMEM write continues in background).
__global__ void __launch_bounds__(32) k_copy_tma(char* __restrict__ dst,
                                                 const char* __restrict__ src,
                                                 long long nchunks) {
    __shared__ alignas(128) char buf[NSTAGE][CP_CHUNK];
    __shared__ alignas(8) unsigned long long mbar[NSTAGE];
    if (threadIdx.x == 0) {
        for (int k = 0; k < NSTAGE; k++) {
            unsigned m = (unsigned)__cvta_generic_to_shared(&mbar[k]);
            asm volatile("mbarrier.init.shared.b64 [%0], 1;" :: "r"(m));
        }
        asm volatile("fence.proxy.async.shared::cta;" ::: "memory");
    }
    __syncthreads();
    if (threadIdx.x != 0) return;

    unsigned ba[NSTAGE], mb[NSTAGE];
    int ph[NSTAGE];
#pragma unroll
    for (int k = 0; k < NSTAGE; k++) {
        ba[k] = (unsigned)__cvta_generic_to_shared(buf[k]);
        mb[k] = (unsigned)__cvta_generic_to_shared(&mbar[k]);
        ph[k] = 0;
    }
    long long stride = gridDim.x;
    long long c0 = blockIdx.x;

    // prologue: fill the pipeline with up to NSTAGE loads
#pragma unroll
    for (int k = 0; k < NSTAGE; k++) {
        long long c = c0 + (long long)k * stride;
        if (c < nchunks) {
            asm volatile("mbarrier.arrive.expect_tx.shared.b64 _, [%0], %1;"
                         :: "r"(mb[k]), "r"(CP_CHUNK));
            asm volatile("cp.async.bulk.shared::cta.global.mbarrier::complete_tx::bytes "
                         "[%0], [%1], %2, [%3];"
                         :: "r"(ba[k]), "l"(src + c * CP_CHUNK), "r"(CP_CHUNK), "r"(mb[k])
                         : "memory");
        }
    }

    int s = 0;
    for (long long c = c0; c < nchunks; c += stride) {
        // wait for this stage's load data
        asm volatile(
            "{\n\t.reg .pred P;\n"
            "WL%=:\n\t"
            "mbarrier.try_wait.parity.shared.b64 P, [%0], %1;\n\t"
            "@P bra DL%=;\n\t"
            "bra WL%=;\n"
            "DL%=:\n\t}"
            :: "r"(mb[s]), "r"(ph[s]) : "memory");
        ph[s] ^= 1;
        // bulk store this chunk
        asm volatile("cp.async.bulk.global.shared::cta.bulk_group [%0], [%1], %2;"
                     :: "l"(dst + c * CP_CHUNK), "r"(ba[s]), "r"(CP_CHUNK) : "memory");
        asm volatile("cp.async.bulk.commit_group;" ::: "memory");
        // refill this stage for chunk c + NSTAGE*stride
        long long pre = c + (long long)NSTAGE * stride;
        if (pre < nchunks) {
            asm volatile("cp.async.bulk.wait_group.read 0;" ::: "memory");
            asm volatile("mbarrier.arrive.expect_tx.shared.b64 _, [%0], %1;"
                         :: "r"(mb[s]), "r"(CP_CHUNK));
            asm volatile("cp.async.bulk.shared::cta.global.mbarrier::complete_tx::bytes "
                         "[%0], [%1], %2, [%3];"
                         :: "r"(ba[s]), "l"(src + pre * CP_CHUNK), "r"(CP_CHUNK), "r"(mb[s])
                         : "memory");
        }
        s = (s + 1) & (NSTAGE - 1);
    }
    asm volatile("cp.async.bulk.wait_group.read 0;" ::: "memory");
}

// -------- tail copy for any bytes not covered by whole chunks --------
__global__ void k_copy_tail(float* __restrict__ dst, const float* __restrict__ src,
                            int start, int n) {
    int i = start + blockIdx.x * blockDim.x + threadIdx.x;
    if (i < n) dst[i] = __ldcs(&src[i]);
}

// -------- scatter-add after join; tail resets scratch for next graph replay --------
__global__ void k_scatter(float* __restrict__ out, const int* __restrict__ rip) {
    int row = blockIdx.x;
    int j = threadIdx.x;
    long long r = (long long)rip[row];
    out[r * D_H + j] += g_h[row * D_H + j];
    // zero scratch state for the next replay (60*128 = 7680 threads)
    int gid = row * D_H + j;
    if (gid < 2048) g_hist1[gid] = 0;
    if (gid >= 2048 && gid < 4096) g_hist2[gid - 2048] = 0;
    if (gid >= 4096 && gid < 5120) g_hist3[gid - 4096] = 0;
    if (gid >= 5120 && gid < 5128) g_state[gid - 5120] = 0;
}

extern "C" void kernel_launch(void* const* d_in, const int* in_sizes, int n_in,
                              void* d_out, int out_size) {
    const float* nf   = (const float*)d_in[0];
    const float* wp   = (const float*)d_in[1];
    const float* mp   = (const float*)d_in[2];
    const float* lat  = (const float*)d_in[3];
    const int*   rip  = (const int*)  d_in[4];
    const float* ln0s = (const float*)d_in[5];
    const float* ln0b = (const float*)d_in[6];
    const float* w1   = (const float*)d_in[7];
    const float* b1   = (const float*)d_in[8];
    const float* w2   = (const float*)d_in[9];
    const float* b2   = (const float*)d_in[10];
    const float* w3   = (const float*)d_in[11];
    const float* b3   = (const float*)d_in[12];
    const float* lnfs = (const float*)d_in[13];
    const float* lnfb = (const float*)d_in[14];
    float* out = (float*)d_out;

    // one-time side-stream + events for the parallel copy branch
    static cudaStream_t s2 = nullptr;
    static cudaEvent_t evFork = nullptr, evJoin = nullptr;
    if (!s2) {
        cudaStreamCreateWithFlags(&s2, cudaStreamNonBlocking);
        cudaEventCreateWithFlags(&evFork, cudaEventDisableTiming);
        cudaEventCreateWithFlags(&evJoin, cudaEventDisableTiming);
    }

    // fork: TMA bulk copy runs concurrently with the select/MLP chain
    cudaEventRecord(evFork, 0);
    cudaStreamWaitEvent(s2, evFork, 0);
    long long nbytes  = (long long)out_size * 4;
    long long nchunks = nbytes / CP_CHUNK;
    k_copy_tma<<<1036, 32, 0, s2>>>((char*)out, (const char*)lat, nchunks);
    int startF = (int)(nchunks * CP_CHUNK / 4);
    if (startF < out_size) {
        int remF = out_size - startF;
        k_copy_tail<<<(remF + 255) / 256, 256, 0, s2>>>(out, lat, startF, out_size);
    }

    // main chain (branch A) — hidden under the copy
    k_keys_hist1<<<1024, 256>>>(nf);
    k_scan<<<1, 256>>>(1);
    k_hist2<<<512, 256>>>();
    k_scan<<<1, 256>>>(2);
    k_hist3<<<512, 256>>>();
    k_scan<<<1, 256>>>(3);
    k_sum<<<SUM_BLOCKS, 256>>>(nf, wp, mp);
    k_finalize<<<1, 64>>>(nf, wp, mp, rip, ln0s, ln0b);
    k_mlp<<<S_RIP, D_H>>>(w1, b1, w2, b2, w3, b3, lnfs, lnfb);

    // join: scatter-add needs both the copy and the MLP result
    cudaEventRecord(evJoin, s2);
    cudaStreamWaitEvent(0, evJoin, 0);
    k_scatter<<<S_RIP, D_H>>>(out, rip);
}

// round 16
// speedup vs baseline: 1.1709x; 1.0039x over previous
#include <cuda_runtime.h>
#include <math.h>

#define N_NODES   1000000
#define K_TOP     10000
#define S_RIP     60
#define D_H       128
#define D_IN      17
#define LN_EPS    1e-5f
#define SUM_BLOCKS 512
#define TIED_CAP  4096

#define NSTAGE    4
#define CP_CHUNK  16384
#define CP_GRID   444
#define CP_SMEM   (NSTAGE * CP_CHUNK + 64)

// -------- device scratch (no allocations allowed) --------
__device__ unsigned int g_keys[N_NODES];
__device__ unsigned int g_hist1[2048];
__device__ unsigned int g_hist2[2048];
__device__ unsigned int g_hist3[1024];
// state: [0]=b1 [1]=K1 [2]=b2 [3]=K2 [4]=T [5]=need [6]=tied_count
__device__ unsigned int g_state[8];
__device__ float        g_partials[SUM_BLOCKS * 8];
__device__ int          g_tied[TIED_CAP];
__device__ float        g_x[S_RIP * D_IN];
__device__ float        g_h[S_RIP * D_H];

// -------- pass 1: keys + level-1 histogram (bits [21:31]) --------
__global__ void k_keys_hist1(const float* __restrict__ nf) {
    __shared__ unsigned int sh[2048];
    for (int i = threadIdx.x; i < 2048; i += blockDim.x) sh[i] = 0;
    __syncthreads();
    int stride = gridDim.x * blockDim.x;
    const float4* nf4 = (const float4*)nf;   // row i starts at float 12*i -> float4 3*i
    for (int i = blockIdx.x * blockDim.x + threadIdx.x; i < N_NODES; i += stride) {
        float4 v = nf4[i * 3];               // v.x,v.y,v.z = velocity
        float s = v.x * v.x + v.y * v.y + v.z * v.z;
        unsigned int u = __float_as_uint(s); // s >= 0: uint order == float order
        g_keys[i] = u;
        atomicAdd(&sh[u >> 21], 1u);
    }
    __syncthreads();
    for (int i = threadIdx.x; i < 2048; i += blockDim.x)
        if (sh[i]) atomicAdd(&g_hist1[i], sh[i]);
}

// -------- level-2 histogram over candidate bucket (bits [10:21]) --------
__global__ void k_hist2() {
    __shared__ unsigned int sh[2048];
    for (int i = threadIdx.x; i < 2048; i += blockDim.x) sh[i] = 0;
    __syncthreads();
    unsigned int b1 = g_state[0];
    int stride = gridDim.x * blockDim.x;
    for (int i = blockIdx.x * blockDim.x + threadIdx.x; i < N_NODES; i += stride) {
        unsigned int u = g_keys[i];
        if ((u >> 21) == b1) atomicAdd(&sh[(u >> 10) & 0x7FFu], 1u);
    }
    __syncthreads();
    for (int i = threadIdx.x; i < 2048; i += blockDim.x)
        if (sh[i]) atomicAdd(&g_hist2[i], sh[i]);
}

// -------- level-3 histogram (bits [0:10]) --------
__global__ void k_hist3() {
    __shared__ unsigned int sh[1024];
    for (int i = threadIdx.x; i < 1024; i += blockDim.x) sh[i] = 0;
    __syncthreads();
    unsigned int prefix21 = (g_state[0] << 11) | g_state[2];
    int stride = gridDim.x * blockDim.x;
    for (int i = blockIdx.x * blockDim.x + threadIdx.x; i < N_NODES; i += stride) {
        unsigned int u = g_keys[i];
        if ((u >> 10) == prefix21) atomicAdd(&sh[u & 0x3FFu], 1u);
    }
    __syncthreads();
    for (int i = threadIdx.x; i < 1024; i += blockDim.x)
        if (sh[i]) atomicAdd(&g_hist3[i], sh[i]);
}

// -------- single-block scan: find bucket containing the K-th largest --------
__global__ void k_scan(int level) {
    __shared__ unsigned int csum[256];
    __shared__ unsigned int suf[256];
    const unsigned int* hist = (level == 1) ? g_hist1 : (level == 2) ? g_hist2 : g_hist3;
    int nbins = (level == 3) ? 1024 : 2048;
    unsigned int K = (level == 1) ? (unsigned int)K_TOP
                   : (level == 2) ? g_state[1] : g_state[3];
    int t = threadIdx.x;
    int chunk = nbins / 256;
    unsigned int s = 0;
    for (int b = t * chunk; b < (t + 1) * chunk; b++) s += hist[b];
    csum[t] = s;
    __syncthreads();
    if (t == 0) {
        unsigned int acc = 0;
        for (int c = 255; c >= 0; c--) { suf[c] = acc; acc += csum[c]; }
    }
    __syncthreads();
    // walk own chunk top-down; exactly one thread finds the bucket
    unsigned int cum = suf[t];
    for (int b = (t + 1) * chunk - 1; b >= t * chunk; b--) {
        unsigned int h = hist[b];
        if (cum < K && cum + h >= K) {
            unsigned int rem = K - cum;
            if (level == 1)      { g_state[0] = (unsigned int)b; g_state[1] = rem; }
            else if (level == 2) { g_state[2] = (unsigned int)b; g_state[3] = rem; }
            else {
                g_state[4] = (g_state[0] << 21) | (g_state[2] << 10) | (unsigned int)b;
                g_state[5] = rem;
            }
        }
        cum += h;
    }
}

// -------- reduction: sums over keys > T; collect ties at == T --------
__global__ void k_sum(const float* __restrict__ nf, const float* __restrict__ wp,
                      const float* __restrict__ mp) {
    unsigned int T = g_state[4];
    float acc[8];
#pragma unroll
    for (int c = 0; c < 8; c++) acc[c] = 0.f;
    int stride = gridDim.x * blockDim.x;
    for (int i = blockIdx.x * blockDim.x + threadIdx.x; i < N_NODES; i += stride) {
        unsigned int u = g_keys[i];
        if (u > T) {
            acc[0] += nf[i * 12 + 0];
            acc[1] += nf[i * 12 + 1];
            acc[2] += nf[i * 12 + 2];
            acc[3] += wp[i * 3 + 0];
            acc[4] += wp[i * 3 + 1];
            acc[5] += wp[i * 3 + 2];
            acc[6] += mp[i * 2 + 0];
            acc[7] += mp[i * 2 + 1];
        } else if (u == T) {
            int p = (int)atomicAdd(&g_state[6], 1u);
            if (p < TIED_CAP) g_tied[p] = i;
        }
    }
    __shared__ float red[256];
    for (int c = 0; c < 8; c++) {
        red[threadIdx.x] = acc[c];
        __syncthreads();
        for (int s = 128; s > 0; s >>= 1) {
            if (threadIdx.x < s) red[threadIdx.x] += red[threadIdx.x + s];
            __syncthreads();
        }
        if (threadIdx.x == 0) g_partials[blockIdx.x * 8 + c] = red[0];
        __syncthreads();
    }
}

// -------- finalize: reduce partials, ties (sorted by index), build x + LN0 --------
__global__ void k_finalize(const float* __restrict__ nf, const float* __restrict__ wp,
                           const float* __restrict__ mp, const int* __restrict__ rip,
                           const float* __restrict__ ln0s, const float* __restrict__ ln0b) {
    __shared__ float hv[8];
    int t = threadIdx.x;
    if (t < 8) {
        float a = 0.f;
        for (int b = 0; b < SUM_BLOCKS; b++) a += g_partials[b * 8 + t];
        hv[t] = a;
    }
    __syncthreads();
    if (t == 0) {
        int cnt = (int)g_state[6];
        if (cnt > TIED_CAP) cnt = TIED_CAP;
        int need = (int)g_state[5];
        // insertion sort ascending -> matches stable lowest-index tie-break
        for (int i = 1; i < cnt; i++) {
            int v = g_tied[i];
            int j = i - 1;
            while (j >= 0 && g_tied[j] > v) { g_tied[j + 1] = g_tied[j]; j--; }
            g_tied[j + 1] = v;
        }
        for (int i = 0; i < need && i < cnt; i++) {
            int idx = g_tied[i];
            hv[0] += nf[idx * 12 + 0];
            hv[1] += nf[idx * 12 + 1];
            hv[2] += nf[idx * 12 + 2];
            hv[3] += wp[idx * 3 + 0];
            hv[4] += wp[idx * 3 + 1];
            hv[5] += wp[idx * 3 + 2];
            hv[6] += mp[idx * 2 + 0];
            hv[7] += mp[idx * 2 + 1];
        }
    }
    __syncthreads();
    if (t < S_RIP) {
        int r = rip[t];
        float x[D_IN];
        x[0] = hv[0]; x[1] = hv[1]; x[2] = hv[2];
        x[3] = hv[0]; x[4] = hv[1]; x[5] = hv[2];
        x[6] = hv[0]; x[7] = hv[1]; x[8] = hv[2];
        x[9]  = nf[r * 12 + 0];
        x[10] = nf[r * 12 + 1];
        x[11] = nf[r * 12 + 2];
        x[12] = wp[r * 3 + 0] - hv[3];
        x[13] = wp[r * 3 + 1] - hv[4];
        x[14] = wp[r * 3 + 2] - hv[5];
        x[15] = mp[r * 2 + 0] - hv[6];
        x[16] = mp[r * 2 + 1] - hv[7];
        float mu = 0.f;
#pragma unroll
        for (int k = 0; k < D_IN; k++) mu += x[k];
        mu *= (1.0f / D_IN);
        float var = 0.f;
#pragma unroll
        for (int k = 0; k < D_IN; k++) { float d = x[k] - mu; var += d * d; }
        var *= (1.0f / D_IN);
        float inv = rsqrtf(var + LN_EPS);
#pragma unroll
        for (int k = 0; k < D_IN; k++)
            g_x[t * D_IN + k] = (x[k] - mu) * inv * ln0s[k] + ln0b[k];
    }
}

// -------- MLP: 60 blocks x 128 threads, one row per block --------
__global__ void k_mlp(const float* __restrict__ w1, const float* __restrict__ b1,
                      const float* __restrict__ w2, const float* __restrict__ b2,
                      const float* __restrict__ w3, const float* __restrict__ b3,
                      const float* __restrict__ lnfs, const float* __restrict__ lnfb) {
    int row = blockIdx.x;
    int j = threadIdx.x;  // 0..127
    __shared__ float sx[D_IN];
    __shared__ float h1[D_H];
    __shared__ float h2[D_H];
    __shared__ float red[D_H];
    if (j < D_IN) sx[j] = g_x[row * D_IN + j];
    __syncthreads();
    float a = b1[j];
#pragma unroll
    for (int k = 0; k < D_IN; k++) a += sx[k] * w1[k * D_H + j];
    h1[j] = fmaxf(a, 0.f);
    __syncthreads();
    a = b2[j];
#pragma unroll 8
    for (int k = 0; k < D_H; k++) a += h1[k] * w2[k * D_H + j];
    h2[j] = fmaxf(a, 0.f);
    __syncthreads();
    a = b3[j];
#pragma unroll 8
    for (int k = 0; k < D_H; k++) a += h2[k] * w3[k * D_H + j];
    // layernorm over 128
    float val = a;
    red[j] = val;
    __syncthreads();
    for (int s = 64; s > 0; s >>= 1) {
        if (j < s) red[j] += red[j + s];
        __syncthreads();
    }
    float mu = red[0] * (1.0f / D_H);
    __syncthreads();
    float d = val - mu;
    red[j] = d * d;
    __syncthreads();
    for (int s = 64; s > 0; s >>= 1) {
        if (j < s) red[j] += red[j + s];
        __syncthreads();
    }
    float var = red[0] * (1.0f / D_H);
    float out = d * rsqrtf(var + LN_EPS) * lnfs[j] + lnfb[j];
    g_h[row * D_H + j] = out;
}

// -------- bulk copy via TMA: cp.async.bulk 16KB bursts, 4-stage SMEM pipeline --------
// Dynamic smem (64KB > 48KB static limit). One control thread per CTA.
__global__ void __launch_bounds__(32) k_copy_tma(char* __restrict__ dst,
                                                 const char* __restrict__ src,
                                                 long long nchunks) {
    extern __shared__ char dyn[];
    char* buf = dyn;                                       // NSTAGE * CP_CHUNK
    unsigned long long* mbar =
        (unsigned long long*)(dyn + NSTAGE * CP_CHUNK);    // NSTAGE barriers
    if (threadIdx.x == 0) {
        for (int k = 0; k < NSTAGE; k++) {
            unsigned m = (unsigned)__cvta_generic_to_shared(&mbar[k]);
            asm volatile("mbarrier.init.shared.b64 [%0], 1;" :: "r"(m));
        }
        asm volatile("fence.proxy.async.shared::cta;" ::: "memory");
    }
    __syncthreads();
    if (threadIdx.x != 0) return;

    unsigned ba[NSTAGE], mb[NSTAGE];
    int ph[NSTAGE];
#pragma unroll
    for (int k = 0; k < NSTAGE; k++) {
        ba[k] = (unsigned)__cvta_generic_to_shared(buf + (size_t)k * CP_CHUNK);
        mb[k] = (unsigned)__cvta_generic_to_shared(&mbar[k]);
        ph[k] = 0;
    }
    long long stride = gridDim.x;
    long long c0 = blockIdx.x;

    // prologue: fill the pipeline with up to NSTAGE loads
#pragma unroll
    for (int k = 0; k < NSTAGE; k++) {
        long long c = c0 + (long long)k * stride;
        if (c < nchunks) {
            asm volatile("mbarrier.arrive.expect_tx.shared.b64 _, [%0], %1;"
                         :: "r"(mb[k]), "r"(CP_CHUNK));
            asm volatile("cp.async.bulk.shared::cta.global.mbarrier::complete_tx::bytes "
                         "[%0], [%1], %2, [%3];"
                         :: "r"(ba[k]), "l"(src + c * CP_CHUNK), "r"(CP_CHUNK), "r"(mb[k])
                         : "memory");
        }
    }

    int s = 0;
    for (long long c = c0; c < nchunks; c += stride) {
        // wait for this stage's load data
        asm volatile(
            "{\n\t.reg .pred P;\n"
            "WL%=:\n\t"
            "mbarrier.try_wait.parity.shared.b64 P, [%0], %1;\n\t"
            "@P bra DL%=;\n\t"
            "bra WL%=;\n"
            "DL%=:\n\t}"
            :: "r"(mb[s]), "r"(ph[s]) : "memory");
        ph[s] ^= 1;
        // bulk store this chunk
        asm volatile("cp.async.bulk.global.shared::cta.bulk_group [%0], [%1], %2;"
                     :: "l"(dst + c * CP_CHUNK), "r"(ba[s]), "r"(CP_CHUNK) : "memory");
        asm volatile("cp.async.bulk.commit_group;" ::: "memory");
        // refill this stage for chunk c + NSTAGE*stride
        long long pre = c + (long long)NSTAGE * stride;
        if (pre < nchunks) {
            asm volatile("cp.async.bulk.wait_group.read 0;" ::: "memory");
            asm volatile("mbarrier.arrive.expect_tx.shared.b64 _, [%0], %1;"
                         :: "r"(mb[s]), "r"(CP_CHUNK));
            asm volatile("cp.async.bulk.shared::cta.global.mbarrier::complete_tx::bytes "
                         "[%0], [%1], %2, [%3];"
                         :: "r"(ba[s]), "l"(src + pre * CP_CHUNK), "r"(CP_CHUNK), "r"(mb[s])
                         : "memory");
        }
        s = (s + 1) & (NSTAGE - 1);
    }
    asm volatile("cp.async.bulk.wait_group.read 0;" ::: "memory");
}

// -------- tail copy for any bytes not covered by whole chunks --------
__global__ void k_copy_tail(float* __restrict__ dst, const float* __restrict__ src,
                            int start, int n) {
    int i = start + blockIdx.x * blockDim.x + threadIdx.x;
    if (i < n) dst[i] = __ldcs(&src[i]);
}

// -------- scatter-add after join; tail resets scratch for next graph replay --------
__global__ void k_scatter(float* __restrict__ out, const int* __restrict__ rip) {
    int row = blockIdx.x;
    int j = threadIdx.x;
    long long r = (long long)rip[row];
    out[r * D_H + j] += g_h[row * D_H + j];
    // zero scratch state for the next replay (60*128 = 7680 threads)
    int gid = row * D_H + j;
    if (gid < 2048) g_hist1[gid] = 0;
    if (gid >= 2048 && gid < 4096) g_hist2[gid - 2048] = 0;
    if (gid >= 4096 && gid < 5120) g_hist3[gid - 4096] = 0;
    if (gid >= 5120 && gid < 5128) g_state[gid - 5120] = 0;
}

extern "C" void kernel_launch(void* const* d_in, const int* in_sizes, int n_in,
                              void* d_out, int out_size) {
    const float* nf   = (const float*)d_in[0];
    const float* wp   = (const float*)d_in[1];
    const float* mp   = (const float*)d_in[2];
    const float* lat  = (const float*)d_in[3];
    const int*   rip  = (const int*)  d_in[4];
    const float* ln0s = (const float*)d_in[5];
    const float* ln0b = (const float*)d_in[6];
    const float* w1   = (const float*)d_in[7];
    const float* b1   = (const float*)d_in[8];
    const float* w2   = (const float*)d_in[9];
    const float* b2   = (const float*)d_in[10];
    const float* w3   = (const float*)d_in[11];
    const float* b3   = (const float*)d_in[12];
    const float* lnfs = (const float*)d_in[13];
    const float* lnfb = (const float*)d_in[14];
    float* out = (float*)d_out;

    // one-time side-stream + events + smem opt-in (first call is uncaptured)
    static cudaStream_t s2 = nullptr;
    static cudaEvent_t evFork = nullptr, evJoin = nullptr;
    if (!s2) {
        cudaStreamCreateWithFlags(&s2, cudaStreamNonBlocking);
        cudaEventCreateWithFlags(&evFork, cudaEventDisableTiming);
        cudaEventCreateWithFlags(&evJoin, cudaEventDisableTiming);
        cudaFuncSetAttribute(k_copy_tma,
                             cudaFuncAttributeMaxDynamicSharedMemorySize, CP_SMEM);
    }

    // fork: TMA bulk copy runs concurrently with the select/MLP chain
    cudaEventRecord(evFork, 0);
    cudaStreamWaitEvent(s2, evFork, 0);
    long long nbytes  = (long long)out_size * 4;
    long long nchunks = nbytes / CP_CHUNK;
    k_copy_tma<<<CP_GRID, 32, CP_SMEM, s2>>>((char*)out, (const char*)lat, nchunks);
    int startF = (int)(nchunks * CP_CHUNK / 4);
    if (startF < out_size) {
        int remF = out_size - startF;
        k_copy_tail<<<(remF + 255) / 256, 256, 0, s2>>>(out, lat, startF, out_size);
    }

    // main chain (branch A) — hidden under the copy
    k_keys_hist1<<<1024, 256>>>(nf);
    k_scan<<<1, 256>>>(1);
    k_hist2<<<512, 256>>>();
    k_scan<<<1, 256>>>(2);
    k_hist3<<<512, 256>>>();
    k_scan<<<1, 256>>>(3);
    k_sum<<<SUM_BLOCKS, 256>>>(nf, wp, mp);
    k_finalize<<<1, 64>>>(nf, wp, mp, rip, ln0s, ln0b);
    k_mlp<<<S_RIP, D_H>>>(w1, b1, w2, b2, w3, b3, lnfs, lnfb);

    // join: scatter-add needs both the copy and the MLP result
    cudaEventRecord(evJoin, s2);
    cudaStreamWaitEvent(0, evJoin, 0);
    k_scatter<<<S_RIP, D_H>>>(out, rip);
}